// round 1
// baseline (speedup 1.0000x reference)
#include <cuda_runtime.h>
#include <cuda_bf16.h>

// Problem constants (fixed for RoIPointPool3d_23845658427905)
#define Bn 4
#define Nn 16384
#define Mn 128
#define Cn 128
#define Sn 512
#define ROW (3 + Cn)          // 131 floats per pooled row
#define NWORDS (Nn / 32)      // 512 ballot words per box
#define NT 512                // threads per block (one block per box)

// Fused kernel: one block per (batch, box).
//  Phase 1: warp-parallel point-in-rotated-box ballots -> shared bitmask (no syncs, pipelined loads)
//  Phase 2: block scan of popcounts -> first-come-ordered index compaction
//  Phase 3: resolve wrap-around sample indices, coalesced gather+write of (S, 131) tile
__global__ __launch_bounds__(NT, 2) void roipool_kernel(
    const float* __restrict__ points,   // (B, N, 3)
    const float* __restrict__ feats,    // (B, N, C)
    const float* __restrict__ boxes,    // (B, M, 7)
    float* __restrict__ out,            // (B, M, S, 131) [+ (B,M) flags]
    int write_flags)
{
    __shared__ unsigned s_words[NWORDS];  // in-box bitmask, word W covers points [32W, 32W+32)
    __shared__ int s_table[Sn];           // first min(cnt, S) in-box point indices, in order
    __shared__ int s_idx[Sn];             // resolved sample index per output row (-1 if empty)
    __shared__ int s_warpSum[16];
    __shared__ int s_total;

    const int bm   = blockIdx.x;          // 0 .. B*M-1
    const int b    = bm >> 7;             // / M (M = 128)
    const int tid  = threadIdx.x;
    const int lane = tid & 31;
    const int wid  = tid >> 5;

    // ---- box parameters (broadcast loads) ----
    const float* box = boxes + bm * 7;
    const float cx = box[0];
    const float cy = box[1];
    const float dx = box[3], dy = box[4], dz = box[5];
    const float rz = box[6];
    const float cz = __fadd_rn(box[2], __fmul_rn(0.5f, dz));  // bottom center -> geometric center
    const float hx = __fmul_rn(0.5f, dx);
    const float hy = __fmul_rn(0.5f, dy);
    const float hz = __fmul_rn(0.5f, dz);
    // correctly-rounded f32 sin/cos of -rz (match jax f32 semantics as closely as possible)
    const double nrz = -(double)rz;
    const float cosa = (float)cos(nrz);
    const float sina = (float)sin(nrz);

    const float* pts = points + (size_t)b * Nn * 3;
    const float* fb  = feats  + (size_t)b * Nn * Cn;

    // ---- Phase 1: ballots, no block syncs (pipelined) ----
    #pragma unroll 4
    for (int W = wid; W < NWORDS; W += NT / 32) {
        const int i = W * 32 + lane;
        const float px = pts[i * 3 + 0];
        const float py = pts[i * 3 + 1];
        const float pz = pts[i * 3 + 2];
        // explicit non-contracted IEEE ops (match XLA per-op HLO rounding)
        const float sx = __fsub_rn(px, cx);
        const float sy = __fsub_rn(py, cy);
        const float lx = __fsub_rn(__fmul_rn(sx, cosa), __fmul_rn(sy, sina));
        const float ly = __fadd_rn(__fmul_rn(sx, sina), __fmul_rn(sy, cosa));
        const bool in =
            (fabsf(__fsub_rn(pz, cz)) <= hz) &&
            (lx > -hx) && (lx < hx) &&
            (ly > -hy) && (ly < hy);
        const unsigned bal = __ballot_sync(0xffffffffu, in);
        if (lane == 0) s_words[W] = bal;
    }
    __syncthreads();

    // ---- Phase 2: block scan of per-word popcounts, ordered compaction ----
    unsigned w = s_words[tid];            // NWORDS == NT == 512
    const int c = __popc(w);
    int incl = c;
    #pragma unroll
    for (int off = 1; off < 32; off <<= 1) {
        int v = __shfl_up_sync(0xffffffffu, incl, off);
        if (lane >= off) incl += v;
    }
    if (lane == 31) s_warpSum[wid] = incl;
    __syncthreads();
    if (wid == 0) {
        int v = (lane < 16) ? s_warpSum[lane] : 0;
        int iv = v;
        #pragma unroll
        for (int off = 1; off < 16; off <<= 1) {
            int t = __shfl_up_sync(0xffffffffu, iv, off);
            if (lane >= off) iv += t;
        }
        if (lane < 16) s_warpSum[lane] = iv - v;  // exclusive warp bases
        if (lane == 15) s_total = iv;             // total in-box count
    }
    __syncthreads();

    int base = s_warpSum[wid] + (incl - c);       // exclusive prefix for this word
    const int word_pt = tid * 32;
    while (w) {
        const int bit = __ffs(w) - 1;
        w &= (w - 1);
        if (base < Sn) s_table[base] = word_pt + bit;
        base++;
    }
    __syncthreads();

    int cnt = s_total;
    if (cnt > Sn) cnt = Sn;                       // j % cnt == j for j < S <= cnt

    // ---- Phase 3a: resolve wrap-around indices (one per output row) ----
    // tid in [0, 512) == [0, Sn)
    s_idx[tid] = (cnt > 0) ? s_table[tid % cnt] : -1;
    __syncthreads();

    // ---- Phase 3b: gather + coalesced write of the (S, 131) tile ----
    float* orow = out + (size_t)bm * Sn * ROW;
    #pragma unroll 4
    for (int e = tid; e < Sn * ROW; e += NT) {
        const int s  = e / ROW;                   // magic-constant division
        const int cc = e - s * ROW;
        const int idx = s_idx[s];
        float v = 0.0f;
        if (idx >= 0) {
            v = (cc < 3) ? pts[idx * 3 + cc]
                         : fb[(size_t)idx * Cn + (cc - 3)];
        }
        orow[e] = v;
    }

    // ---- empty flag (appended after pooled features, as float 0/1) ----
    if (write_flags && tid == 0) {
        out[(size_t)Bn * Mn * Sn * ROW + bm] = (cnt == 0) ? 1.0f : 0.0f;
    }
}

extern "C" void kernel_launch(void* const* d_in, const int* in_sizes, int n_in,
                              void* d_out, int out_size)
{
    const float* points = (const float*)d_in[0];   // (B, N, 3)
    const float* feats  = (const float*)d_in[1];   // (B, N, C)
    const float* boxes  = (const float*)d_in[2];   // (B, M, 7)
    float* out = (float*)d_out;

    const long long pooled = (long long)Bn * Mn * Sn * ROW;   // 34,340,864
    const int write_flags = ((long long)out_size >= pooled + (long long)Bn * Mn) ? 1 : 0;

    roipool_kernel<<<Bn * Mn, NT>>>(points, feats, boxes, out, write_flags);
}